// round 15
// baseline (speedup 1.0000x reference)
#include <cuda_runtime.h>

// LIF neuron scan, T=16:
//   u1 = mem*0.5 + x[t]*0.5 ; spike = (u1 > 1) ; mem = spike ? 0 : u1
//
// FINAL KERNEL — HBM-roofline streaming. 512 MB compulsory 1:1 R/W traffic
// at 6452 GB/s (DRAM 81.4%, 80.7% of 8 TB/s spec) — the measured B300
// path-independent mixed-stream ceiling. Best profile AND best stable wall
// time of a 14-round lever matrix:
//   - per-thread MLP: 1 float4 column best (16-batch neutral R2,
//     2-col + occupancy collapse fatal R3)
//   - cache policy: default beats .cs-both/.cs-ld/.cs-st/.cg-ld
//     (R2/R6/R9/R10)
//   - access width: 256-bit v8 ops neutral (R13) — DRAM cap path-independent
//   - block size: 512 marginally best (R12/R14 > 256-cluster R4/R7/R8/R11)
//   - 32-bit pointer-bump addressing (R7), exact grid 2048x512, no guard
//   - wave-tail quantization irrelevant (R5)

#define TSTEPS 16

__global__ void __launch_bounds__(512)
lif_scan_kernel(const float* __restrict__ x, float* __restrict__ out)
{
    const unsigned col = blockIdx.x * 512u + threadIdx.x;   // 0 .. 2^20-1
    const unsigned stride4 = 1u << 20;                      // float4 cols per timestep

    const float4* __restrict__ xp = reinterpret_cast<const float4*>(x) + col;
    float4* __restrict__ op = reinterpret_cast<float4*>(out) + col;

    float4 mem = make_float4(0.f, 0.f, 0.f, 0.f);

    #pragma unroll
    for (int t = 0; t < TSTEPS; ++t) {
        const float4 xt = *xp;

        float4 s;
        float u;
        u = fmaf(mem.x, 0.5f, xt.x * 0.5f); s.x = (u > 1.f) ? 1.f : 0.f; mem.x = (u > 1.f) ? 0.f : u;
        u = fmaf(mem.y, 0.5f, xt.y * 0.5f); s.y = (u > 1.f) ? 1.f : 0.f; mem.y = (u > 1.f) ? 0.f : u;
        u = fmaf(mem.z, 0.5f, xt.z * 0.5f); s.z = (u > 1.f) ? 1.f : 0.f; mem.z = (u > 1.f) ? 0.f : u;
        u = fmaf(mem.w, 0.5f, xt.w * 0.5f); s.w = (u > 1.f) ? 1.f : 0.f; mem.w = (u > 1.f) ? 0.f : u;

        *op = s;

        xp += stride4;   // single IADD per pointer per step
        op += stride4;
    }
}

extern "C" void kernel_launch(void* const* d_in, const int* in_sizes, int n_in,
                              void* d_out, int out_size)
{
    const float* x = (const float*)d_in[0];
    float* out = (float*)d_out;

    // 67,108,864 elements / 16 timesteps / 4 per float4 / 512 threads = 2048 CTAs exactly.
    lif_scan_kernel<<<2048, 512>>>(x, out);
}